// round 8
// baseline (speedup 1.0000x reference)
#include <cuda_runtime.h>
#include <cuda_bf16.h>

// ---- static problem config ----
#define NIMG 32
#define HH   1024
#define WW   1024
#define BHW  16                 // pool window
#define BSTR 14                 // block stride
#define BC   73                 // blocks per spatial dim
#define BC2  (BC*BC)            // 5329
#define NROW (NIMG*BC)          // 2336  (n, bh) row-blocks
#define NBLK (NROW*BC)          // 170528 total blocks
#define OUT_ELEMS (NBLK*3)      // 511584 floats = 127896 float4 (exact)
#define OUT_VEC4  (OUT_ELEMS/4)
#define THRESH 0.9f
#define W4     (WW/4)

// scratch (device globals — no allocation allowed)
__device__ unsigned g_bitmap[NROW * 3];   // 96-bit active mask per (n,bh) row
__device__ unsigned g_count[NROW];        // popcount per row
__device__ unsigned g_offset[NROW];       // exclusive prefix of counts
__device__ unsigned g_total;              // total active blocks
__device__ unsigned g_done;               // zero-initialized; reset by last CTA

#define SCAN_T   256
#define SCAN_PER ((NROW + SCAN_T - 1) / SCAN_T)   // 10

// ---------------------------------------------------------------------------
// K1: one CTA per (n, bh) — exact R5 structure (proven occ 93.5%, DRAM 71%).
// 256 threads: vertical max over the <=16-row window (coalesced float4,
// 4 columns/thread) -> smem; warps 0-2 compute the 73 horizontal window
// maxima and ballot them into a 96-bit bitmap + count. Zero is the exact
// identity (zero padding, mask values in [0,1)).
// Tail: last-arriving CTA (threadfence + atomic counter) runs the 2336-count
// exclusive scan in-kernel and resets the counter for graph replays.
// ---------------------------------------------------------------------------
__global__ __launch_bounds__(256) void pool_kernel(const float* __restrict__ mask)
{
    const int cta = blockIdx.x;          // n*BC + bh
    const int n   = cta / BC;
    const int bh  = cta % BC;
    const int tid = threadIdx.x;

    __shared__ float sv[WW];
    __shared__ unsigned sbm[3];
    __shared__ unsigned partial[SCAN_T];
    __shared__ bool s_last;

    // padded window [bh*14, bh*14+16) -> unpadded rows [bh*14-1, bh*14+15)
    const int h0 = bh * BSTR - 1;
    const int hs = (h0 < 0) ? 0 : h0;
    const int he = (h0 + BHW < HH) ? (h0 + BHW) : HH;

    const float4* base = (const float4*)(mask + (size_t)n * HH * WW);
    float4 acc = make_float4(0.f, 0.f, 0.f, 0.f);
    #pragma unroll 4
    for (int h = hs; h < he; ++h) {
        float4 x = base[h * W4 + tid];
        acc.x = fmaxf(acc.x, x.x);
        acc.y = fmaxf(acc.y, x.y);
        acc.z = fmaxf(acc.z, x.z);
        acc.w = fmaxf(acc.w, x.w);
    }
    sv[4 * tid + 0] = acc.x;
    sv[4 * tid + 1] = acc.y;
    sv[4 * tid + 2] = acc.z;
    sv[4 * tid + 3] = acc.w;
    __syncthreads();

    if (tid < 96) {                       // warps 0,1,2
        float m = 0.f;
        if (tid < BC) {
            const int w0 = tid * BSTR - 1;
            const int ws = (w0 < 0) ? 0 : w0;
            const int we = (w0 + BHW < WW) ? (w0 + BHW) : WW;
            for (int w = ws; w < we; ++w) m = fmaxf(m, sv[w]);
        }
        unsigned b = __ballot_sync(0xFFFFFFFFu, m > THRESH);
        if ((tid & 31) == 0) sbm[tid >> 5] = b;
    }
    __syncthreads();

    if (tid < 3) g_bitmap[cta * 3 + tid] = sbm[tid];
    if (tid == 0)
        g_count[cta] = (unsigned)(__popc(sbm[0]) + __popc(sbm[1]) + __popc(sbm[2]));

    // ---- last-CTA in-kernel scan (threadFenceReduction pattern) ----
    __threadfence();
    if (tid == 0) {
        unsigned prev = atomicAdd(&g_done, 1u);
        s_last = (prev == (unsigned)gridDim.x - 1u);
    }
    __syncthreads();
    if (!s_last) return;

    // this CTA sees all g_count/g_bitmap writes (fence + atomic ordering)
    const int start = tid * SCAN_PER;
    const int end   = (start + SCAN_PER < NROW) ? (start + SCAN_PER) : NROW;

    unsigned sum = 0;
    for (int i = start; i < end; ++i) sum += g_count[i];
    partial[tid] = sum;
    __syncthreads();

    for (int off = 1; off < SCAN_T; off <<= 1) {
        unsigned t = (tid >= off) ? partial[tid - off] : 0u;
        __syncthreads();
        partial[tid] += t;
        __syncthreads();
    }

    unsigned run = (tid > 0) ? partial[tid - 1] : 0u;
    for (int i = start; i < end; ++i) {        // second pass: L2-hot re-read
        g_offset[i] = run;
        run += g_count[i];
    }
    if (tid == SCAN_T - 1) g_total = partial[tid];
    if (tid == 0) g_done = 0;                  // reset for next graph replay
}

// ---------------------------------------------------------------------------
// Position -> (n, bh, bw) resolution.
// Fast path (total == NBLK): identity divmod. General path: binary search
// last row with offset <= p, then select the rank-th set bit of the bitmap.
// ---------------------------------------------------------------------------
__device__ __forceinline__ int nth_set_bit(unsigned w, int n)  // n-th (0-based)
{
    return (int)__fns(w, 0, n + 1);
}

__device__ __forceinline__ void resolve_pos(unsigned p, unsigned total,
                                            float* t /*[3]*/)
{
    if (p >= total) { t[0] = -1.f; t[1] = -1.f; t[2] = -1.f; return; }

    if (total == NBLK) {   // dense: active block index == block index
        unsigned n = p / BC2;
        unsigned r = p - n * BC2;
        t[0] = (float)n;
        t[1] = (float)(r / BC);
        t[2] = (float)(r % BC);
        return;
    }

    int lo = 0, hi = NROW - 1;
    while (lo < hi) {
        int mid = (lo + hi + 1) >> 1;
        if (g_offset[mid] <= p) lo = mid; else hi = mid - 1;
    }
    int row = lo;
    int rank = (int)(p - g_offset[row]);

    unsigned w0 = g_bitmap[row * 3 + 0];
    unsigned w1 = g_bitmap[row * 3 + 1];
    unsigned w2 = g_bitmap[row * 3 + 2];
    int c0 = __popc(w0), c1 = __popc(w1);
    int bw;
    if (rank < c0)            bw = nth_set_bit(w0, rank);
    else if (rank - c0 < c1)  bw = 32 + nth_set_bit(w1, rank - c0);
    else                      bw = 64 + nth_set_bit(w2, rank - c0 - c1);

    t[0] = (float)(row / BC);
    t[1] = (float)(row % BC);
    t[2] = (float)bw;
}

// ---------------------------------------------------------------------------
// K2: output-driven write. One thread per float4 output slot (4 elements,
// spanning at most 2 consecutive positions). Dense coalesced 16B stores;
// -1 tail handled in the same pass — no fill kernel.
// ---------------------------------------------------------------------------
__global__ __launch_bounds__(256) void write_kernel(float4* __restrict__ out)
{
    const int slot = blockIdx.x * 256 + threadIdx.x;
    if (slot >= OUT_VEC4) return;

    const unsigned total = g_total;
    const unsigned e0 = (unsigned)slot * 4u;
    const unsigned p0 = e0 / 3u;

    float t0[3], t1[3];
    resolve_pos(p0, total, t0);
    resolve_pos(p0 + 1u, total, t1);

    float v[4];
    #pragma unroll
    for (int k = 0; k < 4; ++k) {
        unsigned e = e0 + (unsigned)k;
        unsigned p = e / 3u;
        unsigned c = e - p * 3u;
        v[k] = (p == p0) ? t0[c] : t1[c];
    }
    out[slot] = make_float4(v[0], v[1], v[2], v[3]);
}

// ---------------------------------------------------------------------------
extern "C" void kernel_launch(void* const* d_in, const int* in_sizes, int n_in,
                              void* d_out, int out_size)
{
    const float* mask = (const float*)d_in[0];

    pool_kernel<<<NROW, 256>>>(mask);
    write_kernel<<<(OUT_VEC4 + 255) / 256, 256>>>((float4*)d_out);
}

// round 9
// speedup vs baseline: 1.0410x; 1.0410x over previous
#include <cuda_runtime.h>
#include <cuda_bf16.h>

// ---- static problem config ----
#define NIMG 32
#define HH   1024
#define WW   1024
#define BHW  16                 // pool window
#define BSTR 14                 // block stride
#define BC   73                 // blocks per spatial dim
#define BC2  (BC*BC)            // 5329
#define NROW (NIMG*BC)          // 2336  (n, bh) row-blocks
#define NBLK (NROW*BC)          // 170528 total blocks
#define OUT_ELEMS (NBLK*3)      // 511584 floats = 127896 float4 (exact)
#define OUT_VEC4  (OUT_ELEMS/4)
#define THRESH 0.9f
#define W4     (WW/4)

// scratch (device globals — no allocation allowed)
__device__ unsigned g_bitmap[NROW * 3];   // 96-bit active mask per (n,bh) row
__device__ unsigned g_count[NROW];        // popcount per row

// ---------------------------------------------------------------------------
// K1: one CTA per (n, bh) — exact R5 body (24.7us, occ 93.5%, DRAM 70.8%).
// 256 threads: vertical max over the <=16-row window (coalesced float4,
// 4 columns/thread) -> smem; warps 0-2 compute the 73 horizontal window
// maxima and ballot into a 96-bit bitmap + count. Zero is the exact
// identity (zero padding, mask values in [0,1)).
// ---------------------------------------------------------------------------
__global__ __launch_bounds__(256) void pool_kernel(const float* __restrict__ mask)
{
    const int cta = blockIdx.x;          // n*BC + bh
    const int n   = cta / BC;
    const int bh  = cta % BC;
    const int tid = threadIdx.x;

    __shared__ float sv[WW];
    __shared__ unsigned sbm[3];

    // padded window [bh*14, bh*14+16) -> unpadded rows [bh*14-1, bh*14+15)
    const int h0 = bh * BSTR - 1;
    const int hs = (h0 < 0) ? 0 : h0;
    const int he = (h0 + BHW < HH) ? (h0 + BHW) : HH;

    const float4* base = (const float4*)(mask + (size_t)n * HH * WW);
    float4 acc = make_float4(0.f, 0.f, 0.f, 0.f);
    #pragma unroll 4
    for (int h = hs; h < he; ++h) {
        float4 x = base[h * W4 + tid];
        acc.x = fmaxf(acc.x, x.x);
        acc.y = fmaxf(acc.y, x.y);
        acc.z = fmaxf(acc.z, x.z);
        acc.w = fmaxf(acc.w, x.w);
    }
    sv[4 * tid + 0] = acc.x;
    sv[4 * tid + 1] = acc.y;
    sv[4 * tid + 2] = acc.z;
    sv[4 * tid + 3] = acc.w;
    __syncthreads();

    if (tid < 96) {                       // warps 0,1,2
        float m = 0.f;
        if (tid < BC) {
            const int w0 = tid * BSTR - 1;
            const int ws = (w0 < 0) ? 0 : w0;
            const int we = (w0 + BHW < WW) ? (w0 + BHW) : WW;
            for (int w = ws; w < we; ++w) m = fmaxf(m, sv[w]);
        }
        unsigned b = __ballot_sync(0xFFFFFFFFu, m > THRESH);
        if ((tid & 31) == 0) sbm[tid >> 5] = b;
    }
    __syncthreads();

    if (tid < 3) g_bitmap[cta * 3 + tid] = sbm[tid];
    if (tid == 0)
        g_count[cta] = (unsigned)(__popc(sbm[0]) + __popc(sbm[1]) + __popc(sbm[2]));
}

// ---------------------------------------------------------------------------
// K2: fused scan + output write. Each CTA independently:
//   Phase A: coalesce-loads the 2336 counts into smem, converts them to an
//            exclusive scan in place (blocked + Hillis-Steele on partials).
//            Redundant per CTA, but it's 9.3 KB of L2-hot data — free.
//   Phase B: one float4 output slot per thread. Slot phase (slot % 3) has
//            exactly 3 static lane patterns -> register triples only, NO
//            dynamic array indexing (avoids local-memory spills).
// ---------------------------------------------------------------------------
#define WT      256
#define WCHUNK  ((NROW + WT - 1) / WT)    // 10

__device__ __forceinline__ int nth_set_bit(unsigned w, int n)  // n-th (0-based)
{
    return (int)__fns(w, 0, n + 1);
}

__device__ __forceinline__ void resolve3(unsigned p, unsigned total,
                                         const unsigned* __restrict__ s_off,
                                         float& x, float& y, float& z)
{
    if (p >= total) { x = -1.f; y = -1.f; z = -1.f; return; }

    if (total == NBLK) {   // dense: active index == block index (bench path)
        unsigned n = p / BC2;
        unsigned r = p - n * BC2;
        x = (float)n;
        y = (float)(r / BC);
        z = (float)(r % BC);
        return;
    }

    // general: last row with s_off[row] <= p  (smem binary search)
    int lo = 0, hi = NROW - 1;
    while (lo < hi) {
        int mid = (lo + hi + 1) >> 1;
        if (s_off[mid] <= p) lo = mid; else hi = mid - 1;
    }
    const int row  = lo;
    int       rank = (int)(p - s_off[row]);

    unsigned w0 = g_bitmap[row * 3 + 0];
    unsigned w1 = g_bitmap[row * 3 + 1];
    unsigned w2 = g_bitmap[row * 3 + 2];
    int c0 = __popc(w0), c1 = __popc(w1);
    int bw;
    if (rank < c0)            bw = nth_set_bit(w0, rank);
    else if (rank - c0 < c1)  bw = 32 + nth_set_bit(w1, rank - c0);
    else                      bw = 64 + nth_set_bit(w2, rank - c0 - c1);

    x = (float)(row / BC);
    y = (float)(row % BC);
    z = (float)bw;
}

__global__ __launch_bounds__(WT) void write_kernel(float4* __restrict__ out)
{
    __shared__ unsigned s_off[NROW];      // counts, then exclusive offsets
    __shared__ unsigned s_part[WT];
    __shared__ unsigned s_total;

    const int tid = threadIdx.x;

    // ---- Phase A: local exclusive scan of g_count ----
    for (int i = tid; i < NROW; i += WT) s_off[i] = g_count[i];
    __syncthreads();

    const int start = tid * WCHUNK;
    const int end   = (start + WCHUNK < NROW) ? (start + WCHUNK) : NROW;

    unsigned sum = 0;
    for (int i = start; i < end; ++i) sum += s_off[i];
    s_part[tid] = sum;
    __syncthreads();

    #pragma unroll
    for (int off = 1; off < WT; off <<= 1) {
        unsigned t = (tid >= off) ? s_part[tid - off] : 0u;
        __syncthreads();
        s_part[tid] += t;
        __syncthreads();
    }

    unsigned run = (tid > 0) ? s_part[tid - 1] : 0u;
    for (int i = start; i < end; ++i) {       // in place: own chunk only
        unsigned c = s_off[i];
        s_off[i] = run;
        run += c;
    }
    if (tid == WT - 1) s_total = s_part[WT - 1];
    __syncthreads();

    // ---- Phase B: one float4 slot per thread ----
    const int slot = blockIdx.x * WT + tid;
    if (slot >= OUT_VEC4) return;

    const unsigned total = s_total;
    const unsigned p0 = ((unsigned)slot * 4u) / 3u;

    float a0, a1, a2, b0, b1, b2;
    resolve3(p0,      total, s_off, a0, a1, a2);
    resolve3(p0 + 1u, total, s_off, b0, b1, b2);

    const int phase = slot % 3;               // (4s) mod 3 == s mod 3
    float4 v;
    if (phase == 0)      v = make_float4(a0, a1, a2, b0);
    else if (phase == 1) v = make_float4(a1, a2, b0, b1);
    else                 v = make_float4(a2, b0, b1, b2);
    out[slot] = v;
}

// ---------------------------------------------------------------------------
extern "C" void kernel_launch(void* const* d_in, const int* in_sizes, int n_in,
                              void* d_out, int out_size)
{
    const float* mask = (const float*)d_in[0];

    pool_kernel<<<NROW, 256>>>(mask);
    write_kernel<<<(OUT_VEC4 + WT - 1) / WT, WT>>>((float4*)d_out);
}

// round 10
// speedup vs baseline: 1.1871x; 1.1404x over previous
#include <cuda_runtime.h>
#include <cuda_bf16.h>

// ---- static problem config ----
#define NIMG 32
#define HH   1024
#define WW   1024
#define BHW  16                 // pool window
#define BSTR 14                 // block stride
#define BC   73                 // blocks per spatial dim
#define BC2  (BC*BC)            // 5329
#define NROW (NIMG*BC)          // 2336  (n, bh) row-blocks
#define NBLK (NROW*BC)          // 170528 total blocks
#define OUT_ELEMS (NBLK*3)      // 511584 floats = 127896 float4 (exact)
#define OUT_VEC4  (OUT_ELEMS/4)
#define THRESH 0.9f
#define W4     (WW/4)

// scratch (device globals — no allocation allowed)
__device__ unsigned g_bitmap[NROW * 3];   // 96-bit active mask per (n,bh) row
__device__ unsigned g_count[NROW];        // popcount per row

// ---------------------------------------------------------------------------
// K1: one CTA per (n, bh) — exact R5 body (24.7us, occ 93.5%, DRAM 70.8%).
// 256 threads: vertical max over the <=16-row window (coalesced float4,
// 4 columns/thread) -> smem; warps 0-2 compute the 73 horizontal window
// maxima and ballot into a 96-bit bitmap + count. Zero is the exact
// identity (zero padding, mask values in [0,1)).
// ---------------------------------------------------------------------------
__global__ __launch_bounds__(256) void pool_kernel(const float* __restrict__ mask)
{
    const int cta = blockIdx.x;          // n*BC + bh
    const int n   = cta / BC;
    const int bh  = cta % BC;
    const int tid = threadIdx.x;

    __shared__ float sv[WW];
    __shared__ unsigned sbm[3];

    // padded window [bh*14, bh*14+16) -> unpadded rows [bh*14-1, bh*14+15)
    const int h0 = bh * BSTR - 1;
    const int hs = (h0 < 0) ? 0 : h0;
    const int he = (h0 + BHW < HH) ? (h0 + BHW) : HH;

    const float4* base = (const float4*)(mask + (size_t)n * HH * WW);
    float4 acc = make_float4(0.f, 0.f, 0.f, 0.f);
    #pragma unroll 4
    for (int h = hs; h < he; ++h) {
        float4 x = base[h * W4 + tid];
        acc.x = fmaxf(acc.x, x.x);
        acc.y = fmaxf(acc.y, x.y);
        acc.z = fmaxf(acc.z, x.z);
        acc.w = fmaxf(acc.w, x.w);
    }
    sv[4 * tid + 0] = acc.x;
    sv[4 * tid + 1] = acc.y;
    sv[4 * tid + 2] = acc.z;
    sv[4 * tid + 3] = acc.w;
    __syncthreads();

    if (tid < 96) {                       // warps 0,1,2
        float m = 0.f;
        if (tid < BC) {
            const int w0 = tid * BSTR - 1;
            const int ws = (w0 < 0) ? 0 : w0;
            const int we = (w0 + BHW < WW) ? (w0 + BHW) : WW;
            for (int w = ws; w < we; ++w) m = fmaxf(m, sv[w]);
        }
        unsigned b = __ballot_sync(0xFFFFFFFFu, m > THRESH);
        if ((tid & 31) == 0) sbm[tid >> 5] = b;
    }
    __syncthreads();

    if (tid < 3) g_bitmap[cta * 3 + tid] = sbm[tid];
    if (tid == 0)
        g_count[cta] = (unsigned)(__popc(sbm[0]) + __popc(sbm[1]) + __popc(sbm[2]));
}

// ---------------------------------------------------------------------------
// K2: write. Phase A: fast SUM (not scan) of the 2336 counts -> total.
// If total == NBLK (dense; the bench path), positions are pure divmod and
// no offsets are needed. Only the never-taken-sparse fallback runs the full
// smem scan. Phase B: 2 float4 slots per thread, register-triple phase
// branch (no dynamic indexing -> no local memory).
// ---------------------------------------------------------------------------
#define WT      256
#define WSLOTS  2
#define WGRID   ((OUT_VEC4 + WT*WSLOTS - 1) / (WT*WSLOTS))   // 250
#define WCHUNK  ((NROW + WT - 1) / WT)    // 10

__device__ __forceinline__ int nth_set_bit(unsigned w, int n)  // n-th (0-based)
{
    return (int)__fns(w, 0, n + 1);
}

// dense resolve: p < NBLK guaranteed by caller
__device__ __forceinline__ void resolve_dense(unsigned p,
                                              float& x, float& y, float& z)
{
    unsigned n = p / BC2;
    unsigned r = p - n * BC2;
    x = (float)n;
    y = (float)(r / BC);
    z = (float)(r % BC);
}

// general resolve against smem exclusive offsets
__device__ __forceinline__ void resolve_gen(unsigned p, unsigned total,
                                            const unsigned* __restrict__ s_off,
                                            float& x, float& y, float& z)
{
    if (p >= total) { x = -1.f; y = -1.f; z = -1.f; return; }

    int lo = 0, hi = NROW - 1;
    while (lo < hi) {
        int mid = (lo + hi + 1) >> 1;
        if (s_off[mid] <= p) lo = mid; else hi = mid - 1;
    }
    const int row  = lo;
    int       rank = (int)(p - s_off[row]);

    unsigned w0 = g_bitmap[row * 3 + 0];
    unsigned w1 = g_bitmap[row * 3 + 1];
    unsigned w2 = g_bitmap[row * 3 + 2];
    int c0 = __popc(w0), c1 = __popc(w1);
    int bw;
    if (rank < c0)            bw = nth_set_bit(w0, rank);
    else if (rank - c0 < c1)  bw = 32 + nth_set_bit(w1, rank - c0);
    else                      bw = 64 + nth_set_bit(w2, rank - c0 - c1);

    x = (float)(row / BC);
    y = (float)(row % BC);
    z = (float)bw;
}

__device__ __forceinline__ float4 phase_pack(int phase,
                                             float a0, float a1, float a2,
                                             float b0, float b1, float b2)
{
    if (phase == 0) return make_float4(a0, a1, a2, b0);
    if (phase == 1) return make_float4(a1, a2, b0, b1);
    return make_float4(a2, b0, b1, b2);
}

__global__ __launch_bounds__(WT) void write_kernel(float4* __restrict__ out)
{
    __shared__ unsigned s_off[NROW];          // only used on sparse fallback
    __shared__ unsigned s_wsum[WT / 32];
    __shared__ unsigned s_total;

    const int tid = threadIdx.x;

    // ---- Phase A: total = sum(g_count), independent L2-hot loads ----
    unsigned v = 0;
    #pragma unroll
    for (int k = 0; k < WCHUNK; ++k) {
        int i = k * WT + tid;                 // coalesced, independent
        if (i < NROW) v += g_count[i];
    }
    #pragma unroll
    for (int o = 16; o >= 1; o >>= 1)
        v += __shfl_down_sync(0xFFFFFFFFu, v, o);
    if ((tid & 31) == 0) s_wsum[tid >> 5] = v;
    __syncthreads();
    if (tid == 0) {
        unsigned t = 0;
        #pragma unroll
        for (int w = 0; w < WT / 32; ++w) t += s_wsum[w];
        s_total = t;
    }
    __syncthreads();
    const unsigned total = s_total;

    const bool dense = (total == NBLK);
    if (!dense) {
        // ---- sparse fallback: full exclusive scan into s_off ----
        for (int i = tid; i < NROW; i += WT) s_off[i] = g_count[i];
        __syncthreads();
        // single-thread-per-chunk blocked scan reusing s_wsum as partials
        __shared__ unsigned s_part[WT];
        const int start = tid * WCHUNK;
        const int end   = (start + WCHUNK < NROW) ? (start + WCHUNK) : NROW;
        unsigned sum = 0;
        for (int i = start; i < end; ++i) sum += s_off[i];
        s_part[tid] = sum;
        __syncthreads();
        for (int off = 1; off < WT; off <<= 1) {
            unsigned t = (tid >= off) ? s_part[tid - off] : 0u;
            __syncthreads();
            s_part[tid] += t;
            __syncthreads();
        }
        unsigned run = (tid > 0) ? s_part[tid - 1] : 0u;
        for (int i = start; i < end; ++i) {
            unsigned c = s_off[i];
            s_off[i] = run;
            run += c;
        }
        __syncthreads();
    }

    // ---- Phase B: WSLOTS float4 slots per thread ----
    #pragma unroll
    for (int k = 0; k < WSLOTS; ++k) {
        const int slot = (blockIdx.x * WSLOTS + k) * WT + tid;
        if (slot >= OUT_VEC4) continue;

        const unsigned p0 = ((unsigned)slot * 4u) / 3u;
        float a0, a1, a2, b0, b1, b2;
        if (dense) {                           // p0+1 <= NBLK-? p0 max = 170527
            resolve_dense(p0, a0, a1, a2);
            if (p0 + 1u < NBLK) resolve_dense(p0 + 1u, b0, b1, b2);
            else { b0 = -1.f; b1 = -1.f; b2 = -1.f; }
        } else {
            resolve_gen(p0,      total, s_off, a0, a1, a2);
            resolve_gen(p0 + 1u, total, s_off, b0, b1, b2);
        }

        out[slot] = phase_pack(slot % 3, a0, a1, a2, b0, b1, b2);
    }
}

// ---------------------------------------------------------------------------
extern "C" void kernel_launch(void* const* d_in, const int* in_sizes, int n_in,
                              void* d_out, int out_size)
{
    const float* mask = (const float*)d_in[0];

    pool_kernel<<<NROW, 256>>>(mask);
    write_kernel<<<WGRID, WT>>>((float4*)d_out);
}